// round 4
// baseline (speedup 1.0000x reference)
#include <cuda_runtime.h>
#include <cstdint>

#define N_    32
#define CIN_  64
#define COUT_ 64
#define T_    6
#define V_    512
#define M_    (COUT_ * T_)      // 384 rows of the big GEMM (c*6+t)
#define NEG_FILL -1000.0f
#define SLOPE 0.2f

// Scratch (allocation-free rule: __device__ globals)
__device__ float g_xc[N_ * M_ * V_];   // xc[n][c][t][v]  (25 MB)
__device__ float g_si[N_ * V_];
__device__ float g_sj[N_ * V_];

// ---- packed f32x2 helpers (Blackwell FFMA2; ptxas won't emit from C++) ----
__device__ __forceinline__ unsigned long long pack_dup(float a) {
    unsigned long long r;
    asm("mov.b64 %0, {%1, %1};" : "=l"(r) : "f"(a));
    return r;
}
__device__ __forceinline__ void fma2(unsigned long long& d,
                                     unsigned long long a,
                                     unsigned long long b) {
    asm("fma.rn.f32x2 %0, %1, %2, %0;" : "+l"(d) : "l"(a), "l"(b));
}

// ---------------------------------------------------------------------------
// Kernel A: xc[n,c,t,v] = sum_i conv_w[c,i] * x[n,i,t,v] + conv_b[c]
// ---------------------------------------------------------------------------
__global__ __launch_bounds__(256) void k_conv(const float* __restrict__ x,
                                              const float* __restrict__ w,
                                              const float* __restrict__ b) {
    __shared__ float xs[64][128];   // [i][v]   32 KB
    __shared__ float ws[64][64];    // [c][i]   16 KB
    const int n = blockIdx.z, t = blockIdx.y, bv = blockIdx.x * 128;
    const int tid = threadIdx.x;

#pragma unroll
    for (int r = 0; r < 4; ++r) {
        int f = tid + r * 256;
        int row = f >> 4, c4 = (f & 15) << 2;
        *(float4*)&ws[row][c4] = *(const float4*)(w + row * 64 + c4);
    }
#pragma unroll
    for (int r = 0; r < 8; ++r) {
        int f = tid + r * 256;
        int row = f >> 5, c4 = (f & 31) << 2;
        *(float4*)&xs[row][c4] =
            *(const float4*)(x + (((size_t)n * CIN_ + row) * T_ + t) * V_ + bv + c4);
    }
    __syncthreads();

    const int tx = tid & 31;   // v group (4 v's)
    const int ty = tid >> 5;   // c group (8 c's)
    float acc[8][4];
#pragma unroll
    for (int i = 0; i < 8; ++i)
#pragma unroll
        for (int j = 0; j < 4; ++j) acc[i][j] = 0.f;

#pragma unroll 4
    for (int kk = 0; kk < 64; ++kk) {
        float4 bx = *(float4*)&xs[kk][tx << 2];
#pragma unroll
        for (int cc = 0; cc < 8; ++cc) {
            float a = ws[ty * 8 + cc][kk];
            acc[cc][0] = fmaf(a, bx.x, acc[cc][0]);
            acc[cc][1] = fmaf(a, bx.y, acc[cc][1]);
            acc[cc][2] = fmaf(a, bx.z, acc[cc][2]);
            acc[cc][3] = fmaf(a, bx.w, acc[cc][3]);
        }
    }
#pragma unroll
    for (int cc = 0; cc < 8; ++cc) {
        int c = ty * 8 + cc;
        float bias = b[c];
        float4 o = make_float4(acc[cc][0] + bias, acc[cc][1] + bias,
                               acc[cc][2] + bias, acc[cc][3] + bias);
        *(float4*)(g_xc + (((size_t)n * COUT_ + c) * T_ + t) * V_ + bv + (tx << 2)) = o;
    }
}

// ---------------------------------------------------------------------------
// Kernel B: folded attention-score projections. 128 v's per block.
// ---------------------------------------------------------------------------
__global__ __launch_bounds__(128) void k_scores(const float* __restrict__ l1_w,
                                                const float* __restrict__ l2_w,
                                                const float* __restrict__ l2_b) {
    const int n = blockIdx.y;
    const int v = blockIdx.x * 128 + threadIdx.x;
    const int tid = threadIdx.x;
    __shared__ float cs[M_], cd[M_];
#pragma unroll
    for (int r = 0; r < 3; ++r) {
        int m = tid + r * 128;
        int c = m / T_, t = m % T_;
        float lw = l2_w[t];
        cs[m] = lw * l1_w[c];
        cd[m] = lw * l1_w[COUT_ + c];
    }
    __syncthreads();

    float si = 0.f, sj = 0.f;
    const float* xp = g_xc + (size_t)n * M_ * V_ + v;
#pragma unroll 8
    for (int m = 0; m < M_; ++m) {
        float xv = xp[(size_t)m * V_];
        si = fmaf(xv, cs[m], si);
        sj = fmaf(xv, cd[m], sj);
    }
    float ss = 0.f, sd = 0.f;
#pragma unroll
    for (int c = 0; c < COUT_; ++c) { ss += l1_w[c]; sd += l1_w[COUT_ + c]; }
    float lb = l2_b[0];
    g_si[n * V_ + v] = si + lb * ss;
    g_sj[n * V_ + v] = sj + lb * sd;
}

// ---------------------------------------------------------------------------
// Kernel C: per (n,v) row: leaky_relu(s_i+s_j+b), mask fill -1000, softmax.
// 512 threads (one per w), warp-shuffle reductions.
// ---------------------------------------------------------------------------
__global__ __launch_bounds__(512) void k_softmax(const float* __restrict__ A,
                                                 const float* __restrict__ l1_b,
                                                 float* __restrict__ a4) {
    const int v = blockIdx.x, n = blockIdx.y, tid = threadIdx.x;
    const int lane = tid & 31, wrp = tid >> 5;
    __shared__ float red[16];

    const float siv = g_si[n * V_ + v] + l1_b[0];
    const float* mrow = A + (((size_t)n * 8 + 7) * V_ + v) * V_;
    const float* sjn = g_sj + n * V_;

    float sc = siv + sjn[tid];
    float a1 = sc >= 0.f ? sc : SLOPE * sc;
    float val = (mrow[tid] == 0.f) ? NEG_FILL : a1;

    // block max
    float m = val;
#pragma unroll
    for (int s = 16; s > 0; s >>= 1) m = fmaxf(m, __shfl_xor_sync(~0u, m, s));
    if (lane == 0) red[wrp] = m;
    __syncthreads();
    if (wrp == 0) {
        float t = red[lane & 15];
#pragma unroll
        for (int s = 8; s > 0; s >>= 1) t = fmaxf(t, __shfl_xor_sync(~0u, t, s));
        red[lane & 15] = t;   // all 16 slots end up holding the max
    }
    __syncthreads();
    float mx = red[0];

    float e = __expf(val - mx);
    float su = e;
#pragma unroll
    for (int s = 16; s > 0; s >>= 1) su += __shfl_xor_sync(~0u, su, s);
    if (lane == 0) red[wrp] = su;
    __syncthreads();
    if (wrp == 0) {
        float t = red[lane & 15];
#pragma unroll
        for (int s = 8; s > 0; s >>= 1) t += __shfl_xor_sync(~0u, t, s);
        red[lane & 15] = t;
    }
    __syncthreads();
    float inv = 1.0f / red[0];

    a4[((size_t)n * V_ + v) * V_ + tid] = e * inv;
}

// ---------------------------------------------------------------------------
// Kernel D: out[n] (384x512) = xc[n] (384x512) @ a4[n] (512x512)
// 128x128x8 double-buffered SGEMM, 256 threads, 8x8 microtile computed as
// 8x4 packed f32x2 accumulators via fma.rn.f32x2 (2 MACs/instr).
// ---------------------------------------------------------------------------
__global__ __launch_bounds__(256) void k_gemm(const float* __restrict__ A4,
                                              float* __restrict__ OUT) {
    const int n = blockIdx.z;
    const float* Ap = g_xc + (size_t)n * M_ * V_;        // [384][512]
    const float* Bp = A4 + (size_t)n * V_ * V_;          // [512][512]
    float* Cp = OUT + (size_t)n * M_ * V_;

    const int bm = blockIdx.y * 128, bn = blockIdx.x * 128;
    const int tid = threadIdx.x;

    __shared__ float As[2][8][128];   // transposed A tile, 2 buffers
    __shared__ float Bs[2][8][128];

    const int a_row = tid >> 1, a_col = (tid & 1) * 4;   // 128x8 tile
    const int b_row = tid >> 5, b_col = (tid & 31) * 4;  // 8x128 tile
    const int tx = tid & 15, ty = tid >> 4;

    const float* ApT = Ap + (size_t)(bm + a_row) * V_ + a_col;
    const float* BpT = Bp + (size_t)b_row * V_ + bn + b_col;

    unsigned long long acc2[8][4];
#pragma unroll
    for (int i = 0; i < 8; ++i)
#pragma unroll
        for (int j = 0; j < 4; ++j) acc2[i][j] = 0ull;

    // preload tile 0 into buffer 0
    {
        float4 av = *(const float4*)(ApT);
        As[0][a_col + 0][a_row] = av.x;
        As[0][a_col + 1][a_row] = av.y;
        As[0][a_col + 2][a_row] = av.z;
        As[0][a_col + 3][a_row] = av.w;
        *(float4*)&Bs[0][b_row][b_col] = *(const float4*)(BpT);
    }
    __syncthreads();

    int cur = 0;
    for (int k0 = 0; k0 < V_; k0 += 8) {
        float4 av, bv;
        const bool more = (k0 + 8) < V_;
        if (more) {
            av = *(const float4*)(ApT + k0 + 8);
            bv = *(const float4*)(BpT + (size_t)(k0 + 8) * V_);
        }

#pragma unroll
        for (int k = 0; k < 8; ++k) {
            float4 a0 = *(float4*)&As[cur][k][ty * 8];
            float4 a1 = *(float4*)&As[cur][k][ty * 8 + 4];
            ulonglong2 b01 = *(ulonglong2*)&Bs[cur][k][tx * 8];
            ulonglong2 b23 = *(ulonglong2*)&Bs[cur][k][tx * 8 + 4];
            unsigned long long bp0 = b01.x, bp1 = b01.y, bp2 = b23.x, bp3 = b23.y;
            float af[8] = {a0.x, a0.y, a0.z, a0.w, a1.x, a1.y, a1.z, a1.w};
#pragma unroll
            for (int i = 0; i < 8; ++i) {
                unsigned long long ad = pack_dup(af[i]);
                fma2(acc2[i][0], ad, bp0);
                fma2(acc2[i][1], ad, bp1);
                fma2(acc2[i][2], ad, bp2);
                fma2(acc2[i][3], ad, bp3);
            }
        }

        if (more) {
            int nxt = cur ^ 1;
            As[nxt][a_col + 0][a_row] = av.x;
            As[nxt][a_col + 1][a_row] = av.y;
            As[nxt][a_col + 2][a_row] = av.z;
            As[nxt][a_col + 3][a_row] = av.w;
            *(float4*)&Bs[nxt][b_row][b_col] = bv;
            __syncthreads();
        }
        cur ^= 1;
    }

#pragma unroll
    for (int i = 0; i < 8; ++i) {
        float* cp = Cp + (size_t)(bm + ty * 8 + i) * V_ + bn + tx * 8;
        ulonglong2 o0, o1;
        o0.x = acc2[i][0]; o0.y = acc2[i][1];
        o1.x = acc2[i][2]; o1.y = acc2[i][3];
        *(ulonglong2*)cp = o0;
        *(ulonglong2*)(cp + 4) = o1;
    }
}

// ---------------------------------------------------------------------------
extern "C" void kernel_launch(void* const* d_in, const int* in_sizes, int n_in,
                              void* d_out, int out_size) {
    const float* x      = (const float*)d_in[0];
    const float* A      = (const float*)d_in[1];
    const float* conv_w = (const float*)d_in[2];
    const float* conv_b = (const float*)d_in[3];
    const float* l1_w   = (const float*)d_in[4];
    const float* l1_b   = (const float*)d_in[5];
    const float* l2_w   = (const float*)d_in[6];
    const float* l2_b   = (const float*)d_in[7];

    float* out = (float*)d_out;                       // (32,64,6,512)
    float* a4  = out + (size_t)N_ * COUT_ * T_ * V_;  // (32,1,512,512)

    k_conv<<<dim3(V_ / 128, T_, N_), 256>>>(x, conv_w, conv_b);
    k_scores<<<dim3(V_ / 128, N_), 128>>>(l1_w, l2_w, l2_b);
    k_softmax<<<dim3(V_, N_), 512>>>(A, l1_b, a4);
    k_gemm<<<dim3(V_ / 128, M_ / 128, N_), 256>>>(a4, out);
}

// round 6
// speedup vs baseline: 1.8121x; 1.8121x over previous
#include <cuda_runtime.h>
#include <cstdint>

#define N_    32
#define CIN_  64
#define COUT_ 64
#define T_    6
#define V_    512
#define M_    (COUT_ * T_)      // 384 rows of the big GEMM (c*6+t)
#define NEG_FILL -1000.0f
#define SLOPE 0.2f

// Scratch (allocation-free rule: __device__ globals)
__device__ float g_xc[N_ * M_ * V_];   // xc[n][c][t][v]  (25 MB)
__device__ float g_si[N_ * V_];
__device__ float g_sj[N_ * V_];

__device__ __forceinline__ uint32_t f2tf32(float f) {
    uint32_t r;
    asm("cvt.rna.tf32.f32 %0, %1;" : "=r"(r) : "f"(f));
    return r;
}

// ---------------------------------------------------------------------------
// Kernel A: xc[n,c,t,v] = sum_i conv_w[c,i] * x[n,i,t,v] + conv_b[c]
// ---------------------------------------------------------------------------
__global__ __launch_bounds__(256) void k_conv(const float* __restrict__ x,
                                              const float* __restrict__ w,
                                              const float* __restrict__ b) {
    __shared__ float xs[64][128];
    __shared__ float ws[64][64];
    const int n = blockIdx.z, t = blockIdx.y, bv = blockIdx.x * 128;
    const int tid = threadIdx.x;

#pragma unroll
    for (int r = 0; r < 4; ++r) {
        int f = tid + r * 256;
        int row = f >> 4, c4 = (f & 15) << 2;
        *(float4*)&ws[row][c4] = *(const float4*)(w + row * 64 + c4);
    }
#pragma unroll
    for (int r = 0; r < 8; ++r) {
        int f = tid + r * 256;
        int row = f >> 5, c4 = (f & 31) << 2;
        *(float4*)&xs[row][c4] =
            *(const float4*)(x + (((size_t)n * CIN_ + row) * T_ + t) * V_ + bv + c4);
    }
    __syncthreads();

    const int tx = tid & 31;
    const int ty = tid >> 5;
    float acc[8][4];
#pragma unroll
    for (int i = 0; i < 8; ++i)
#pragma unroll
        for (int j = 0; j < 4; ++j) acc[i][j] = 0.f;

#pragma unroll 4
    for (int kk = 0; kk < 64; ++kk) {
        float4 bx = *(float4*)&xs[kk][tx << 2];
#pragma unroll
        for (int cc = 0; cc < 8; ++cc) {
            float a = ws[ty * 8 + cc][kk];
            acc[cc][0] = fmaf(a, bx.x, acc[cc][0]);
            acc[cc][1] = fmaf(a, bx.y, acc[cc][1]);
            acc[cc][2] = fmaf(a, bx.z, acc[cc][2]);
            acc[cc][3] = fmaf(a, bx.w, acc[cc][3]);
        }
    }
#pragma unroll
    for (int cc = 0; cc < 8; ++cc) {
        int c = ty * 8 + cc;
        float bias = b[c];
        float4 o = make_float4(acc[cc][0] + bias, acc[cc][1] + bias,
                               acc[cc][2] + bias, acc[cc][3] + bias);
        *(float4*)(g_xc + (((size_t)n * COUT_ + c) * T_ + t) * V_ + bv + (tx << 2)) = o;
    }
}

// ---------------------------------------------------------------------------
// Kernel B: folded attention-score projections. 128 v's per block.
// ---------------------------------------------------------------------------
__global__ __launch_bounds__(128) void k_scores(const float* __restrict__ l1_w,
                                                const float* __restrict__ l2_w,
                                                const float* __restrict__ l2_b) {
    const int n = blockIdx.y;
    const int v = blockIdx.x * 128 + threadIdx.x;
    const int tid = threadIdx.x;
    __shared__ float cs[M_], cd[M_];
#pragma unroll
    for (int r = 0; r < 3; ++r) {
        int m = tid + r * 128;
        int c = m / T_, t = m % T_;
        float lw = l2_w[t];
        cs[m] = lw * l1_w[c];
        cd[m] = lw * l1_w[COUT_ + c];
    }
    __syncthreads();

    float si = 0.f, sj = 0.f;
    const float* xp = g_xc + (size_t)n * M_ * V_ + v;
#pragma unroll 8
    for (int m = 0; m < M_; ++m) {
        float xv = xp[(size_t)m * V_];
        si = fmaf(xv, cs[m], si);
        sj = fmaf(xv, cd[m], sj);
    }
    float ss = 0.f, sd = 0.f;
#pragma unroll
    for (int c = 0; c < COUT_; ++c) { ss += l1_w[c]; sd += l1_w[COUT_ + c]; }
    float lb = l2_b[0];
    g_si[n * V_ + v] = si + lb * ss;
    g_sj[n * V_ + v] = sj + lb * sd;
}

// ---------------------------------------------------------------------------
// Kernel C: per (n,v) row: leaky_relu(s_i+s_j+b), mask fill -1000, softmax.
// ---------------------------------------------------------------------------
__global__ __launch_bounds__(512) void k_softmax(const float* __restrict__ A,
                                                 const float* __restrict__ l1_b,
                                                 float* __restrict__ a4) {
    const int v = blockIdx.x, n = blockIdx.y, tid = threadIdx.x;
    const int lane = tid & 31, wrp = tid >> 5;
    __shared__ float red[16];

    const float siv = g_si[n * V_ + v] + l1_b[0];
    const float* mrow = A + (((size_t)n * 8 + 7) * V_ + v) * V_;
    const float* sjn = g_sj + n * V_;

    float sc = siv + sjn[tid];
    float a1 = sc >= 0.f ? sc : SLOPE * sc;
    float val = (mrow[tid] == 0.f) ? NEG_FILL : a1;

    float m = val;
#pragma unroll
    for (int s = 16; s > 0; s >>= 1) m = fmaxf(m, __shfl_xor_sync(~0u, m, s));
    if (lane == 0) red[wrp] = m;
    __syncthreads();
    if (wrp == 0) {
        float t = red[lane & 15];
#pragma unroll
        for (int s = 8; s > 0; s >>= 1) t = fmaxf(t, __shfl_xor_sync(~0u, t, s));
        red[lane & 15] = t;
    }
    __syncthreads();
    float mx = red[0];

    float e = __expf(val - mx);
    float su = e;
#pragma unroll
    for (int s = 16; s > 0; s >>= 1) su += __shfl_xor_sync(~0u, su, s);
    if (lane == 0) red[wrp] = su;
    __syncthreads();
    if (wrp == 0) {
        float t = red[lane & 15];
#pragma unroll
        for (int s = 8; s > 0; s >>= 1) t += __shfl_xor_sync(~0u, t, s);
        red[lane & 15] = t;
    }
    __syncthreads();
    float inv = 1.0f / red[0];

    a4[((size_t)n * V_ + v) * V_ + tid] = e * inv;
}

// ---------------------------------------------------------------------------
// Kernel D (mma.sync tf32): out[n] (384x512) = xc[n] @ a4[n]
// 128x128 block tile, 8 warps (4M x 2N), warp tile 32x64 (2x8 m16n8k8 frags),
// K-chunks of 32, register-staged double-buffered smem.
// ---------------------------------------------------------------------------
#define BM 128
#define BN 128
#define KC 32
#define NCHUNK (V_ / KC)   // 16
#define PA 36              // A smem pitch (floats): (36g+tq)%32 bijective
#define PB 136             // B smem pitch (floats): (136tq+g)%32 bijective
#define SM_GEMM ((2 * BM * PA + 2 * KC * PB) * 4)   // 71,680 B

__global__ __launch_bounds__(256) void k_gemm_mma(const float* __restrict__ A4,
                                                  float* __restrict__ OUT) {
    extern __shared__ float sm[];
    const int tid = threadIdx.x, wid = tid >> 5, lane = tid & 31;
    const int n = blockIdx.z, bm = blockIdx.y * BM, bn = blockIdx.x * BN;

    const float* Ap = g_xc + ((size_t)n * M_ + bm) * V_;   // [128][512]
    const float* Bp = A4 + (size_t)n * V_ * V_ + bn;       // rows [512], cols bn..bn+127

    float* AsB = sm;                  // 2 x [128][PA]
    float* BsB = sm + 2 * BM * PA;    // 2 x [KC][PB]

    const int g = lane >> 2, tq = lane & 3;
    const int warpM = (wid & 3) * 32, warpN = (wid >> 2) * 64;

    float acc[2][8][4];
#pragma unroll
    for (int mt = 0; mt < 2; ++mt)
#pragma unroll
        for (int nt = 0; nt < 8; ++nt)
#pragma unroll
            for (int q = 0; q < 4; ++q) acc[mt][nt][q] = 0.f;

    float4 ar[4], br[4];

#define LOADG(kc) do {                                                          \
    _Pragma("unroll")                                                           \
    for (int r = 0; r < 4; ++r) {                                               \
        int idx = tid + r * 256;                                                \
        ar[r] = *(const float4*)(Ap + (size_t)(idx >> 3) * V_ + (kc) + (idx & 7) * 4); \
        br[r] = *(const float4*)(Bp + (size_t)((kc) + (idx >> 5)) * V_ + (idx & 31) * 4); \
    }                                                                           \
} while (0)

#define STORES(buf) do {                                                        \
    float* Asb = AsB + (buf) * BM * PA;                                         \
    float* Bsb = BsB + (buf) * KC * PB;                                         \
    _Pragma("unroll")                                                           \
    for (int r = 0; r < 4; ++r) {                                               \
        int idx = tid + r * 256;                                                \
        float* pa = Asb + (idx >> 3) * PA + (idx & 7) * 4;                      \
        pa[0] = __uint_as_float(f2tf32(ar[r].x));                               \
        pa[1] = __uint_as_float(f2tf32(ar[r].y));                               \
        pa[2] = __uint_as_float(f2tf32(ar[r].z));                               \
        pa[3] = __uint_as_float(f2tf32(ar[r].w));                               \
        float* pb = Bsb + (idx >> 5) * PB + (idx & 31) * 4;                     \
        pb[0] = __uint_as_float(f2tf32(br[r].x));                               \
        pb[1] = __uint_as_float(f2tf32(br[r].y));                               \
        pb[2] = __uint_as_float(f2tf32(br[r].z));                               \
        pb[3] = __uint_as_float(f2tf32(br[r].w));                               \
    }                                                                           \
} while (0)

    LOADG(0);
    STORES(0);
    __syncthreads();

    int buf = 0;
    for (int c = 0; c < NCHUNK; ++c) {
        const bool more = (c + 1) < NCHUNK;
        if (more) LOADG((c + 1) * KC);

        const float* Asb = AsB + buf * BM * PA;
        const float* Bsb = BsB + buf * KC * PB;
#pragma unroll
        for (int ks = 0; ks < 4; ++ks) {
            const int k0 = ks * 8;
            uint32_t a[2][4], b[8][2];
#pragma unroll
            for (int mt = 0; mt < 2; ++mt) {
                const float* base = Asb + (warpM + mt * 16 + g) * PA + k0 + tq;
                a[mt][0] = __float_as_uint(base[0]);
                a[mt][1] = __float_as_uint(base[8 * PA]);
                a[mt][2] = __float_as_uint(base[4]);
                a[mt][3] = __float_as_uint(base[8 * PA + 4]);
            }
#pragma unroll
            for (int nt = 0; nt < 8; ++nt) {
                const float* base = Bsb + (k0 + tq) * PB + warpN + nt * 8 + g;
                b[nt][0] = __float_as_uint(base[0]);
                b[nt][1] = __float_as_uint(base[4 * PB]);
            }
#pragma unroll
            for (int mt = 0; mt < 2; ++mt)
#pragma unroll
                for (int nt = 0; nt < 8; ++nt)
                    asm volatile(
                        "mma.sync.aligned.m16n8k8.row.col.f32.tf32.tf32.f32 "
                        "{%0,%1,%2,%3}, {%4,%5,%6,%7}, {%8,%9}, {%0,%1,%2,%3};"
                        : "+f"(acc[mt][nt][0]), "+f"(acc[mt][nt][1]),
                          "+f"(acc[mt][nt][2]), "+f"(acc[mt][nt][3])
                        : "r"(a[mt][0]), "r"(a[mt][1]), "r"(a[mt][2]), "r"(a[mt][3]),
                          "r"(b[nt][0]), "r"(b[nt][1]));
        }

        if (more) {
            STORES(buf ^ 1);
            __syncthreads();
        }
        buf ^= 1;
    }

    // epilogue: d0:(g,2tq) d1:(g,2tq+1) d2:(g+8,2tq) d3:(g+8,2tq+1)
#pragma unroll
    for (int mt = 0; mt < 2; ++mt)
#pragma unroll
        for (int nt = 0; nt < 8; ++nt) {
            int row0 = bm + warpM + mt * 16 + g;
            int col = bn + warpN + nt * 8 + 2 * tq;
            float* o0 = OUT + ((size_t)n * M_ + row0) * V_ + col;
            *(float2*)o0 = make_float2(acc[mt][nt][0], acc[mt][nt][1]);
            float* o1 = o0 + 8 * V_;
            *(float2*)o1 = make_float2(acc[mt][nt][2], acc[mt][nt][3]);
        }
}

// ---------------------------------------------------------------------------
extern "C" void kernel_launch(void* const* d_in, const int* in_sizes, int n_in,
                              void* d_out, int out_size) {
    const float* x      = (const float*)d_in[0];
    const float* A      = (const float*)d_in[1];
    const float* conv_w = (const float*)d_in[2];
    const float* conv_b = (const float*)d_in[3];
    const float* l1_w   = (const float*)d_in[4];
    const float* l1_b   = (const float*)d_in[5];
    const float* l2_w   = (const float*)d_in[6];
    const float* l2_b   = (const float*)d_in[7];

    float* out = (float*)d_out;                       // (32,64,6,512)
    float* a4  = out + (size_t)N_ * COUT_ * T_ * V_;  // (32,1,512,512)

    cudaFuncSetAttribute(k_gemm_mma, cudaFuncAttributeMaxDynamicSharedMemorySize, SM_GEMM);

    k_conv<<<dim3(V_ / 128, T_, N_), 256>>>(x, conv_w, conv_b);
    k_scores<<<dim3(V_ / 128, N_), 128>>>(l1_w, l2_w, l2_b);
    k_softmax<<<dim3(V_, N_), 512>>>(A, l1_b, a4);
    k_gemm_mma<<<dim3(V_ / BN, M_ / BM, N_), 256, SM_GEMM>>>(a4, out);
}

// round 7
// speedup vs baseline: 2.5301x; 1.3962x over previous
#include <cuda_runtime.h>
#include <cstdint>

#define N_    32
#define CIN_  64
#define COUT_ 64
#define T_    6
#define V_    512
#define M_    (COUT_ * T_)      // 384 rows of the big GEMM (c*6+t)
#define NEG_FILL -1000.0f
#define SLOPE 0.2f

// Scratch (allocation-free rule: __device__ globals)
__device__ float g_xc[N_ * M_ * V_];   // xc[n][c][t][v]  (25 MB)
__device__ float g_ps[N_ * T_ * V_];   // partial: sum_c w_src[c]*xc[c,t,v]
__device__ float g_pd[N_ * T_ * V_];   // partial: sum_c w_dst[c]*xc[c,t,v]
__device__ float g_si[N_ * V_];
__device__ float g_sj[N_ * V_];

__device__ __forceinline__ uint32_t f2tf32(float f) {
    uint32_t r;
    asm("cvt.rna.tf32.f32 %0, %1;" : "=r"(r) : "f"(f));
    return r;
}

// ---------------------------------------------------------------------------
// Kernel A: xc[n,c,t,v] = sum_i conv_w[c,i] * x[n,i,t,v] + conv_b[c]
// PLUS fused score partials: g_ps/g_pd[n,t,v] = sum_c w_{src,dst}[c]*xc[c,t,v]
// ---------------------------------------------------------------------------
__global__ __launch_bounds__(256) void k_conv(const float* __restrict__ x,
                                              const float* __restrict__ w,
                                              const float* __restrict__ b,
                                              const float* __restrict__ l1_w) {
    __shared__ float xs[64][128];   // 32 KB (reused as reduction buffer later)
    __shared__ float ws[64][64];    // 16 KB
    const int n = blockIdx.z, t = blockIdx.y, bv = blockIdx.x * 128;
    const int tid = threadIdx.x;

#pragma unroll
    for (int r = 0; r < 4; ++r) {
        int f = tid + r * 256;
        int row = f >> 4, c4 = (f & 15) << 2;
        *(float4*)&ws[row][c4] = *(const float4*)(w + row * 64 + c4);
    }
#pragma unroll
    for (int r = 0; r < 8; ++r) {
        int f = tid + r * 256;
        int row = f >> 5, c4 = (f & 31) << 2;
        *(float4*)&xs[row][c4] =
            *(const float4*)(x + (((size_t)n * CIN_ + row) * T_ + t) * V_ + bv + c4);
    }
    __syncthreads();

    const int tx = tid & 31;   // v group (4 v's)
    const int ty = tid >> 5;   // c group (8 c's)
    float acc[8][4];
#pragma unroll
    for (int i = 0; i < 8; ++i)
#pragma unroll
        for (int j = 0; j < 4; ++j) acc[i][j] = 0.f;

#pragma unroll 4
    for (int kk = 0; kk < 64; ++kk) {
        float4 bx = *(float4*)&xs[kk][tx << 2];
#pragma unroll
        for (int cc = 0; cc < 8; ++cc) {
            float a = ws[ty * 8 + cc][kk];
            acc[cc][0] = fmaf(a, bx.x, acc[cc][0]);
            acc[cc][1] = fmaf(a, bx.y, acc[cc][1]);
            acc[cc][2] = fmaf(a, bx.z, acc[cc][2]);
            acc[cc][3] = fmaf(a, bx.w, acc[cc][3]);
        }
    }

    // add bias into acc (xc includes bias), store xc, accumulate partials
    float ls[4] = {0.f, 0.f, 0.f, 0.f}, ld[4] = {0.f, 0.f, 0.f, 0.f};
#pragma unroll
    for (int cc = 0; cc < 8; ++cc) {
        int c = ty * 8 + cc;
        float bias = b[c];
        float wsrc = __ldg(l1_w + c);
        float wdst = __ldg(l1_w + COUT_ + c);
#pragma unroll
        for (int j = 0; j < 4; ++j) {
            acc[cc][j] += bias;
            ls[j] = fmaf(wsrc, acc[cc][j], ls[j]);
            ld[j] = fmaf(wdst, acc[cc][j], ld[j]);
        }
        *(float4*)(g_xc + (((size_t)n * COUT_ + c) * T_ + t) * V_ + bv + (tx << 2)) =
            make_float4(acc[cc][0], acc[cc][1], acc[cc][2], acc[cc][3]);
    }

    // reduce partials over the 8 c-groups (reuse xs storage)
    float* red = &xs[0][0];   // [0..1023]=src, [1024..2047]=dst
    __syncthreads();          // everyone done reading xs
    *(float4*)&red[ty * 128 + tx * 4]        = make_float4(ls[0], ls[1], ls[2], ls[3]);
    *(float4*)&red[1024 + ty * 128 + tx * 4] = make_float4(ld[0], ld[1], ld[2], ld[3]);
    __syncthreads();

    {
        int sel = tid >> 7;          // 0 = src, 1 = dst
        int v = tid & 127;
        float s = 0.f;
#pragma unroll
        for (int r = 0; r < 8; ++r) s += red[sel * 1024 + r * 128 + v];
        float* dst = sel ? g_pd : g_ps;
        dst[((size_t)n * T_ + t) * V_ + bv + v] = s;
    }
}

// ---------------------------------------------------------------------------
// Kernel B': fold t-partials into si/sj. 32 blocks x 512 threads.
// ---------------------------------------------------------------------------
__global__ __launch_bounds__(512) void k_finish(const float* __restrict__ l1_w,
                                                const float* __restrict__ l2_w,
                                                const float* __restrict__ l2_b) {
    const int n = blockIdx.x, v = threadIdx.x;
    float si = 0.f, sj = 0.f;
#pragma unroll
    for (int t = 0; t < T_; ++t) {
        float lw = __ldg(l2_w + t);
        si = fmaf(lw, g_ps[((size_t)n * T_ + t) * V_ + v], si);
        sj = fmaf(lw, g_pd[((size_t)n * T_ + t) * V_ + v], sj);
    }
    float ss = 0.f, sd = 0.f;
#pragma unroll
    for (int c = 0; c < COUT_; ++c) { ss += __ldg(l1_w + c); sd += __ldg(l1_w + COUT_ + c); }
    float lb = l2_b[0];
    g_si[n * V_ + v] = si + lb * ss;
    g_sj[n * V_ + v] = sj + lb * sd;
}

// ---------------------------------------------------------------------------
// Kernel C: per (n,v) row softmax, 128 threads x float4.
// ---------------------------------------------------------------------------
__global__ __launch_bounds__(128) void k_softmax(const float* __restrict__ A,
                                                 const float* __restrict__ l1_b,
                                                 float* __restrict__ a4) {
    const int v = blockIdx.x, n = blockIdx.y, tid = threadIdx.x;
    const int lane = tid & 31, wrp = tid >> 5;
    __shared__ float red[4];

    const float siv = g_si[n * V_ + v] + l1_b[0];
    const float* mrow = A + (((size_t)n * 8 + 7) * V_ + v) * V_;
    const float* sjn = g_sj + n * V_;

    float4 sj4 = *(const float4*)(sjn + tid * 4);
    float4 mk4 = *(const float4*)(mrow + tid * 4);

    float vals[4];
    {
        float s0 = siv + sj4.x, s1 = siv + sj4.y, s2 = siv + sj4.z, s3 = siv + sj4.w;
        s0 = s0 >= 0.f ? s0 : SLOPE * s0;
        s1 = s1 >= 0.f ? s1 : SLOPE * s1;
        s2 = s2 >= 0.f ? s2 : SLOPE * s2;
        s3 = s3 >= 0.f ? s3 : SLOPE * s3;
        vals[0] = (mk4.x == 0.f) ? NEG_FILL : s0;
        vals[1] = (mk4.y == 0.f) ? NEG_FILL : s1;
        vals[2] = (mk4.z == 0.f) ? NEG_FILL : s2;
        vals[3] = (mk4.w == 0.f) ? NEG_FILL : s3;
    }

    float m = fmaxf(fmaxf(vals[0], vals[1]), fmaxf(vals[2], vals[3]));
#pragma unroll
    for (int s = 16; s > 0; s >>= 1) m = fmaxf(m, __shfl_xor_sync(~0u, m, s));
    if (lane == 0) red[wrp] = m;
    __syncthreads();
    float mx = fmaxf(fmaxf(red[0], red[1]), fmaxf(red[2], red[3]));
    __syncthreads();

    float e0 = __expf(vals[0] - mx);
    float e1 = __expf(vals[1] - mx);
    float e2 = __expf(vals[2] - mx);
    float e3 = __expf(vals[3] - mx);
    float su = (e0 + e1) + (e2 + e3);
#pragma unroll
    for (int s = 16; s > 0; s >>= 1) su += __shfl_xor_sync(~0u, su, s);
    if (lane == 0) red[wrp] = su;
    __syncthreads();
    float inv = 1.0f / (((red[0] + red[1]) + (red[2] + red[3])));

    *(float4*)(a4 + ((size_t)n * V_ + v) * V_ + tid * 4) =
        make_float4(e0 * inv, e1 * inv, e2 * inv, e3 * inv);
}

// ---------------------------------------------------------------------------
// Kernel D (mma.sync tf32): out[n] (384x512) = xc[n] @ a4[n]
// 128x128 block tile, 8 warps (4M x 2N), warp tile 32x64 (2x8 m16n8k8 frags),
// K-chunks of 32, register-staged double-buffered smem.
// ---------------------------------------------------------------------------
#define BM 128
#define BN 128
#define KC 32
#define NCHUNK (V_ / KC)   // 16
#define PA 36              // A smem pitch (floats)
#define PB 136             // B smem pitch (floats)
#define SM_GEMM ((2 * BM * PA + 2 * KC * PB) * 4)   // 71,680 B

__global__ __launch_bounds__(256) void k_gemm_mma(const float* __restrict__ A4,
                                                  float* __restrict__ OUT) {
    extern __shared__ float sm[];
    const int tid = threadIdx.x, wid = tid >> 5, lane = tid & 31;
    const int n = blockIdx.z, bm = blockIdx.y * BM, bn = blockIdx.x * BN;

    const float* Ap = g_xc + ((size_t)n * M_ + bm) * V_;   // [128][512]
    const float* Bp = A4 + (size_t)n * V_ * V_ + bn;

    float* AsB = sm;                  // 2 x [128][PA]
    float* BsB = sm + 2 * BM * PA;    // 2 x [KC][PB]

    const int g = lane >> 2, tq = lane & 3;
    const int warpM = (wid & 3) * 32, warpN = (wid >> 2) * 64;

    float acc[2][8][4];
#pragma unroll
    for (int mt = 0; mt < 2; ++mt)
#pragma unroll
        for (int nt = 0; nt < 8; ++nt)
#pragma unroll
            for (int q = 0; q < 4; ++q) acc[mt][nt][q] = 0.f;

    float4 ar[4], br[4];

#define LOADG(kc) do {                                                          \
    _Pragma("unroll")                                                           \
    for (int r = 0; r < 4; ++r) {                                               \
        int idx = tid + r * 256;                                                \
        ar[r] = *(const float4*)(Ap + (size_t)(idx >> 3) * V_ + (kc) + (idx & 7) * 4); \
        br[r] = *(const float4*)(Bp + (size_t)((kc) + (idx >> 5)) * V_ + (idx & 31) * 4); \
    }                                                                           \
} while (0)

#define STORES(buf) do {                                                        \
    float* Asb = AsB + (buf) * BM * PA;                                         \
    float* Bsb = BsB + (buf) * KC * PB;                                         \
    _Pragma("unroll")                                                           \
    for (int r = 0; r < 4; ++r) {                                               \
        int idx = tid + r * 256;                                                \
        float* pa = Asb + (idx >> 3) * PA + (idx & 7) * 4;                      \
        pa[0] = __uint_as_float(f2tf32(ar[r].x));                               \
        pa[1] = __uint_as_float(f2tf32(ar[r].y));                               \
        pa[2] = __uint_as_float(f2tf32(ar[r].z));                               \
        pa[3] = __uint_as_float(f2tf32(ar[r].w));                               \
        float* pb = Bsb + (idx >> 5) * PB + (idx & 31) * 4;                     \
        pb[0] = __uint_as_float(f2tf32(br[r].x));                               \
        pb[1] = __uint_as_float(f2tf32(br[r].y));                               \
        pb[2] = __uint_as_float(f2tf32(br[r].z));                               \
        pb[3] = __uint_as_float(f2tf32(br[r].w));                               \
    }                                                                           \
} while (0)

    LOADG(0);
    STORES(0);
    __syncthreads();

    int buf = 0;
    for (int c = 0; c < NCHUNK; ++c) {
        const bool more = (c + 1) < NCHUNK;
        if (more) LOADG((c + 1) * KC);

        const float* Asb = AsB + buf * BM * PA;
        const float* Bsb = BsB + buf * KC * PB;
#pragma unroll
        for (int ks = 0; ks < 4; ++ks) {
            const int k0 = ks * 8;
            uint32_t a[2][4], b[8][2];
#pragma unroll
            for (int mt = 0; mt < 2; ++mt) {
                const float* base = Asb + (warpM + mt * 16 + g) * PA + k0 + tq;
                a[mt][0] = __float_as_uint(base[0]);
                a[mt][1] = __float_as_uint(base[8 * PA]);
                a[mt][2] = __float_as_uint(base[4]);
                a[mt][3] = __float_as_uint(base[8 * PA + 4]);
            }
#pragma unroll
            for (int nt = 0; nt < 8; ++nt) {
                const float* base = Bsb + (k0 + tq) * PB + warpN + nt * 8 + g;
                b[nt][0] = __float_as_uint(base[0]);
                b[nt][1] = __float_as_uint(base[4 * PB]);
            }
#pragma unroll
            for (int mt = 0; mt < 2; ++mt)
#pragma unroll
                for (int nt = 0; nt < 8; ++nt)
                    asm volatile(
                        "mma.sync.aligned.m16n8k8.row.col.f32.tf32.tf32.f32 "
                        "{%0,%1,%2,%3}, {%4,%5,%6,%7}, {%8,%9}, {%0,%1,%2,%3};"
                        : "+f"(acc[mt][nt][0]), "+f"(acc[mt][nt][1]),
                          "+f"(acc[mt][nt][2]), "+f"(acc[mt][nt][3])
                        : "r"(a[mt][0]), "r"(a[mt][1]), "r"(a[mt][2]), "r"(a[mt][3]),
                          "r"(b[nt][0]), "r"(b[nt][1]));
        }

        if (more) {
            STORES(buf ^ 1);
            __syncthreads();
        }
        buf ^= 1;
    }

#pragma unroll
    for (int mt = 0; mt < 2; ++mt)
#pragma unroll
        for (int nt = 0; nt < 8; ++nt) {
            int row0 = bm + warpM + mt * 16 + g;
            int col = bn + warpN + nt * 8 + 2 * tq;
            float* o0 = OUT + ((size_t)n * M_ + row0) * V_ + col;
            *(float2*)o0 = make_float2(acc[mt][nt][0], acc[mt][nt][1]);
            float* o1 = o0 + 8 * V_;
            *(float2*)o1 = make_float2(acc[mt][nt][2], acc[mt][nt][3]);
        }
}

// ---------------------------------------------------------------------------
extern "C" void kernel_launch(void* const* d_in, const int* in_sizes, int n_in,
                              void* d_out, int out_size) {
    const float* x      = (const float*)d_in[0];
    const float* A      = (const float*)d_in[1];
    const float* conv_w = (const float*)d_in[2];
    const float* conv_b = (const float*)d_in[3];
    const float* l1_w   = (const float*)d_in[4];
    const float* l1_b   = (const float*)d_in[5];
    const float* l2_w   = (const float*)d_in[6];
    const float* l2_b   = (const float*)d_in[7];

    float* out = (float*)d_out;                       // (32,64,6,512)
    float* a4  = out + (size_t)N_ * COUT_ * T_ * V_;  // (32,1,512,512)

    cudaFuncSetAttribute(k_gemm_mma, cudaFuncAttributeMaxDynamicSharedMemorySize, SM_GEMM);

    k_conv<<<dim3(V_ / 128, T_, N_), 256>>>(x, conv_w, conv_b, l1_w);
    k_finish<<<N_, V_>>>(l1_w, l2_w, l2_b);
    k_softmax<<<dim3(V_, N_), 128>>>(A, l1_b, a4);
    k_gemm_mma<<<dim3(V_ / BN, M_ / BM, N_), 256, SM_GEMM>>>(a4, out);
}